// round 15
// baseline (speedup 1.0000x reference)
#include <cuda_runtime.h>
#include <cuda_bf16.h>
#include <math.h>
#include <float.h>
#include <stdint.h>

// ---------------- problem constants ----------------
#define S0 19997
#define VHEAD 20000
#define V1 20000
#define V2 160000
#define V3 67738
#define KD0 1024
#define KD1 256
#define KD2 64
#define KD3 16
#define NROWS 1024

#define WOFF0 0
#define WOFF1 20480000
#define WOFF2 25600000
#define WOFF3 35840000
#define WTOT  36923808

#define POFF0 0
#define POFF1 1048576
#define POFF2 1310720
#define POFF3 1376256
#define PTOT  1392640

// partial exp-sum chunk layout: jobs 0,1 vspan=256; jobs 2,3 vspan=1024
#define CH_STRIDE 382
#define CH_OFF0 0
#define CH_N0   79
#define CH_OFF1 79
#define CH_N1   79
#define CH_OFF2 158
#define CH_N2   157
#define CH_OFF3 315
#define CH_N3   67

// ---------------- device scratch ----------------
__device__ __align__(16) __nv_bfloat16 g_Wbf[WTOT];
__device__ __align__(16) __nv_bfloat16 g_hbf[NROWS * KD0];
__device__ __align__(16) __nv_bfloat16 g_pTbf[PTOT];
__device__ __align__(16) float         g_projf[PTOT];
__device__ __align__(16) __nv_bfloat16 g_projbf[PTOT];
__device__ float         g_partials[NROWS * CH_STRIDE];
__device__ int           g_t64flag;

__device__ __forceinline__ void cpa16(uint32_t saddr, const void* g) {
    asm volatile("cp.async.cg.shared.global [%0], [%1], 16;\n" :: "r"(saddr), "l"(g));
}

// ---------------- target dtype detection ----------------
__global__ void k_detect(const unsigned int* __restrict__ t) {
    __shared__ int anynz;
    if (threadIdx.x == 0) anynz = 0;
    __syncthreads();
    if (t[2 * threadIdx.x + 1] != 0u) atomicOr(&anynz, 1);
    __syncthreads();
    if (threadIdx.x == 0) g_t64flag = anynz ? 0 : 1;
}

// ---------------- merged prep: wide convert + transpose-convert, ONE launch ----
struct CvSegs {
    const float* src[6];
    __nv_bfloat16* dst[6];
    long long cum[7];
};
struct TcJobs {
    const float* src[4];
    __nv_bfloat16* dst[4];
    int ncols[4];
    int start[4];
};
struct PrepArgs {
    CvSegs cv;
    TcJobs tc;
    long long total16;
    int cvBlocks;
};

__global__ __launch_bounds__(256) void k_prep(PrepArgs a) {
    if ((int)blockIdx.x < a.cvBlocks) {
        long long i = (long long)blockIdx.x * 256 + threadIdx.x;
        if (i >= a.total16) return;
        int j = 0;
#pragma unroll
        for (int k = 1; k < 6; k++)
            if (i >= a.cv.cum[k]) j = k;
        long long off = i - a.cv.cum[j];
        const float4* sp = reinterpret_cast<const float4*>(a.cv.src[j]) + off * 4;
        float4 v0 = sp[0], v1 = sp[1], v2 = sp[2], v3 = sp[3];
        union { __nv_bfloat162 h[4]; uint4 u; } o0, o1;
        o0.h[0] = __floats2bfloat162_rn(v0.x, v0.y);
        o0.h[1] = __floats2bfloat162_rn(v0.z, v0.w);
        o0.h[2] = __floats2bfloat162_rn(v1.x, v1.y);
        o0.h[3] = __floats2bfloat162_rn(v1.z, v1.w);
        o1.h[0] = __floats2bfloat162_rn(v2.x, v2.y);
        o1.h[1] = __floats2bfloat162_rn(v2.z, v2.w);
        o1.h[2] = __floats2bfloat162_rn(v3.x, v3.y);
        o1.h[3] = __floats2bfloat162_rn(v3.z, v3.w);
        uint4* dp = reinterpret_cast<uint4*>(a.cv.dst[j]) + off * 2;
        dp[0] = o0.u;
        dp[1] = o1.u;
    } else {
        __shared__ float tile[32][33];
        int bx2 = blockIdx.x - a.cvBlocks;
        int xt = bx2 % 43;
        int byi = bx2 / 43;
        int ji = 3;
        if (xt < a.tc.start[1]) ji = 0;
        else if (xt < a.tc.start[2]) ji = 1;
        else if (xt < a.tc.start[3]) ji = 2;
        const float* src = a.tc.src[ji];
        __nv_bfloat16* dst = a.tc.dst[ji];
        const int ncols = a.tc.ncols[ji];
        int bx = (xt - a.tc.start[ji]) * 32;
        int by = byi * 32;
        int tx = threadIdx.x & 31, ty = threadIdx.x >> 5;
#pragma unroll
        for (int i = ty; i < 32; i += 8) {
            int k = by + i, j = bx + tx;
            if (j < ncols) tile[i][tx] = src[(size_t)k * ncols + j];
        }
        __syncthreads();
#pragma unroll
        for (int i = ty; i < 32; i += 8) {
            int j = bx + i, k = by + tx;
            if (j < ncols) dst[(size_t)j * 1024 + k] = __float2bfloat16(tile[tx][i]);
        }
    }
}

// ============================================================================
// Projection GEMM (mma.sync), 2-stage cp.async pipeline (race-free ordering).
// Tiles 64x64x64, K = 1024 always.
// ============================================================================
#define GBM 64
#define GBN 64
#define GBK 64
#define SAST 80
#define PASZ (GBM * SAST)
#define PSTGB (2 * PASZ * 2)

__device__ __forceinline__ void proj_pf(
    const __nv_bfloat16* __restrict__ A, const __nv_bfloat16* __restrict__ B,
    int V, int K, int mBase, int vb, int kb, int slot, uint32_t sbase, int tid)
{
    uint32_t sA = sbase + (uint32_t)slot * PSTGB;
    uint32_t sB = sA + (uint32_t)PASZ * 2u;
#pragma unroll
    for (int i = 0; i < 2; i++) {
        int v = tid + i * 256;
        int row = v >> 3, cv = v & 7;
        int gk = kb + cv * 8;
        cpa16(sA + (uint32_t)(row * SAST + cv * 8) * 2u,
              A + (size_t)(mBase + row) * K + gk);
        int gr = vb + row;
        if (gr < V)
            cpa16(sB + (uint32_t)(row * SAST + cv * 8) * 2u,
                  B + (size_t)gr * K + gk);
    }
}

__device__ __forceinline__ void proj_tile(
    const __nv_bfloat16* __restrict__ A,
    const __nv_bfloat16* __restrict__ B,
    int V, int K, int mBase, int vb,
    float* __restrict__ Cf, __nv_bfloat16* __restrict__ Cbf,
    uint32_t sbase)
{
    const int tid = threadIdx.x;
    const int lane = tid & 31, wid = tid >> 5;
    const int mwarp = wid >> 1, nwarp = wid & 1;

    float acc[4][4];
#pragma unroll
    for (int a = 0; a < 4; a++)
#pragma unroll
        for (int b = 0; b < 4; b++) acc[a][b] = 0.f;

    const int nk = K / GBK;
    // race-free 2-stage: pf(0), pf(1); loop { wait 1; sync; compute; sync; pf(ik+2) }
    proj_pf(A, B, V, K, mBase, vb, 0, 0, sbase, tid);
    asm volatile("cp.async.commit_group;\n" ::);
    if (1 < nk) proj_pf(A, B, V, K, mBase, vb, GBK, 1, sbase, tid);
    asm volatile("cp.async.commit_group;\n" ::);

    for (int ik = 0; ik < nk; ik++) {
        asm volatile("cp.async.wait_group 1;\n" ::);
        __syncthreads();

        uint32_t sAu = sbase + (uint32_t)(ik & 1) * PSTGB;
        uint32_t sBu = sAu + (uint32_t)PASZ * 2u;
#pragma unroll
        for (int kk = 0; kk < 4; kk++) {
            uint32_t a0, a1, a2, a3;
            {
                int ar = mwarp * 16 + (lane & 15);
                int ac = kk * 16 + (lane >> 4) * 8;
                uint32_t addr = sAu + (uint32_t)(ar * SAST + ac) * 2u;
                asm volatile("ldmatrix.sync.aligned.m8n8.x4.shared.b16 {%0,%1,%2,%3}, [%4];"
                             : "=r"(a0), "=r"(a1), "=r"(a2), "=r"(a3) : "r"(addr));
            }
#pragma unroll
            for (int nt = 0; nt < 4; nt++) {
                uint32_t b0r, b1r;
                int br = nwarp * 32 + nt * 8 + (lane & 7);
                int bc = kk * 16 + ((lane >> 3) & 1) * 8;
                uint32_t addr = sBu + (uint32_t)(br * SAST + bc) * 2u;
                asm volatile("ldmatrix.sync.aligned.m8n8.x2.shared.b16 {%0,%1}, [%2];"
                             : "=r"(b0r), "=r"(b1r) : "r"(addr));
                asm volatile(
                    "mma.sync.aligned.m16n8k16.row.col.f32.bf16.bf16.f32 "
                    "{%0,%1,%2,%3}, {%4,%5,%6,%7}, {%8,%9}, {%0,%1,%2,%3};"
                    : "+f"(acc[nt][0]), "+f"(acc[nt][1]), "+f"(acc[nt][2]), "+f"(acc[nt][3])
                    : "r"(a0), "r"(a1), "r"(a2), "r"(a3), "r"(b0r), "r"(b1r));
            }
        }
        __syncthreads();
        if (ik + 2 < nk)
            proj_pf(A, B, V, K, mBase, vb, (ik + 2) * GBK, ik & 1, sbase, tid);
        asm volatile("cp.async.commit_group;\n" ::);
    }

    const int g = lane >> 2, t4 = lane & 3;
    const int r0 = mBase + mwarp * 16 + g, r1 = r0 + 8;
#pragma unroll
    for (int nt = 0; nt < 4; nt++) {
        int n0 = vb + nwarp * 32 + nt * 8 + t4 * 2;
        if (n0 < V) {
            Cf[(size_t)r0 * V + n0]     = acc[nt][0];
            Cf[(size_t)r0 * V + n0 + 1] = acc[nt][1];
            Cf[(size_t)r1 * V + n0]     = acc[nt][2];
            Cf[(size_t)r1 * V + n0 + 1] = acc[nt][3];
            Cbf[(size_t)r0 * V + n0]     = __float2bfloat16(acc[nt][0]);
            Cbf[(size_t)r0 * V + n0 + 1] = __float2bfloat16(acc[nt][1]);
            Cbf[(size_t)r1 * V + n0]     = __float2bfloat16(acc[nt][2]);
            Cbf[(size_t)r1 * V + n0 + 1] = __float2bfloat16(acc[nt][3]);
        }
    }
}

__global__ __launch_bounds__(256) void k_proj(
    const __nv_bfloat16* __restrict__ A, const __nv_bfloat16* __restrict__ pT,
    float* __restrict__ projf, __nv_bfloat16* __restrict__ projbf)
{
    __shared__ __align__(16) __nv_bfloat16 smem[2 * 2 * PASZ];
    uint32_t sbase = (uint32_t)__cvta_generic_to_shared(smem);
    int x = blockIdx.x;
    int mBase = blockIdx.y * GBM;
    if (x < 16)
        proj_tile(A, pT + POFF0, 1024, 1024, mBase, x * GBN, projf + POFF0, projbf + POFF0, sbase);
    else if (x < 20)
        proj_tile(A, pT + POFF1, 256, 1024, mBase, (x - 16) * GBN, projf + POFF1, projbf + POFF1, sbase);
    else if (x == 20)
        proj_tile(A, pT + POFF2, 64, 1024, mBase, 0, projf + POFF2, projbf + POFF2, sbase);
    else
        proj_tile(A, pT + POFF3, 16, 1024, mBase, 0, projf + POFF3, projbf + POFF3, sbase);
}

// ============================================================================
// Merged fused logits + exp-sum GEMM. Tiles 64x128x64, 8 warps = 2(M) x 4(N),
// acc 32 fp32/thread, __launch_bounds__(256,3) -> 24 warps/SM.
// Generic (K>64): 2-stage A+B ring (race-free double-barrier).
// K<=64: A resident + 3-stage B ring (single barrier), kk = K/16.
// ============================================================================
#define LBM 64
#define LBN 128
#define LBK 64
#define LST 72
#define ASZ (LBM * LST)            // 4608 halves = 9216 B
#define BSZ (LBN * LST)            // 9216 halves = 18432 B
#define NSTG 2
#define BSTG 3
// K<=64 layout: A(9216) + 3*B(18432) + bias(4096) = 68608; generic 2*(27648)=55296
#define SMEM_DYN 68608

struct LseJob {
    const __nv_bfloat16* A;
    const __nv_bfloat16* B;
    const float* bias0;
    const float* bias1;
    int V, K, bsplit, start, vspan;
};
struct LseJobs { LseJob j[4]; };

// generic prefetch: A 64x64 + B 128x64
__device__ __forceinline__ void lse_prefetch(
    const __nv_bfloat16* __restrict__ A, const __nv_bfloat16* __restrict__ B,
    int V, int K, int mBase, int vb0, int nkb, int it, int slot,
    uint32_t sbase, int tid)
{
    int vbi = it / nkb, kbi = it - vbi * nkb;
    int vb = vb0 + vbi * LBN;
    int kb = kbi * LBK;
    uint32_t sA = sbase + (uint32_t)(slot * (ASZ + BSZ)) * 2u;
    uint32_t sB = sA + (uint32_t)ASZ * 2u;
#pragma unroll
    for (int i = 0; i < 2; i++) {            // A: 64 rows x 8 chunks = 512
        int v = tid + i * 256;
        int row = v >> 3, cv = v & 7;
        cpa16(sA + (uint32_t)(row * LST + cv * 8) * 2u,
              A + (size_t)(mBase + row) * K + kb + cv * 8);
    }
#pragma unroll
    for (int i = 0; i < 4; i++) {            // B: 128 rows x 8 chunks = 1024
        int v = tid + i * 256;
        int row = v >> 3, cv = v & 7;
        int gr = vb + row;
        if (gr < V)
            cpa16(sB + (uint32_t)(row * LST + cv * 8) * 2u,
                  B + (size_t)gr * K + kb + cv * 8);
    }
}

__device__ __forceinline__ void lse_prefetch_b(
    const __nv_bfloat16* __restrict__ B,
    int V, int K, int vb, int slot,
    uint32_t sbase, int tid)
{
    uint32_t sB = sbase + (uint32_t)(ASZ + slot * BSZ) * 2u;
#pragma unroll
    for (int i = 0; i < 4; i++) {
        int v = tid + i * 256;
        int row = v >> 3, cv = v & 7;
        int gr = vb + row;
        if (gr < V && cv * 8 < K)
            cpa16(sB + (uint32_t)(row * LST + cv * 8) * 2u,
                  B + (size_t)gr * K + cv * 8);
    }
}

// compute one 64x128 tile: warps 2(M) x 4(N); acc[2][4][4]
template <int NKK>
__device__ __forceinline__ void lse_mma_tile(
    uint32_t sAu, uint32_t sBu, int lane, int mw, int nw, float acc[2][4][4])
{
#pragma unroll
    for (int kk = 0; kk < NKK; kk++) {
        uint32_t a[2][4];
#pragma unroll
        for (int mt = 0; mt < 2; mt++) {
            int ar = mw * 32 + mt * 16 + (lane & 15);
            int ac = kk * 16 + (lane >> 4) * 8;
            uint32_t addr = sAu + (uint32_t)(ar * LST + ac) * 2u;
            asm volatile("ldmatrix.sync.aligned.m8n8.x4.shared.b16 {%0,%1,%2,%3}, [%4];"
                         : "=r"(a[mt][0]), "=r"(a[mt][1]), "=r"(a[mt][2]), "=r"(a[mt][3])
                         : "r"(addr));
        }
        uint32_t b[2][4];
#pragma unroll
        for (int np = 0; np < 2; np++) {
            int q = lane >> 3;
            int br = nw * 32 + np * 16 + (q >> 1) * 8 + (lane & 7);
            int bc = kk * 16 + (q & 1) * 8;
            uint32_t addr = sBu + (uint32_t)(br * LST + bc) * 2u;
            asm volatile("ldmatrix.sync.aligned.m8n8.x4.shared.b16 {%0,%1,%2,%3}, [%4];"
                         : "=r"(b[np][0]), "=r"(b[np][1]), "=r"(b[np][2]), "=r"(b[np][3])
                         : "r"(addr));
        }
#pragma unroll
        for (int mt = 0; mt < 2; mt++)
#pragma unroll
            for (int nt = 0; nt < 4; nt++) {
                uint32_t bb0 = b[nt >> 1][(nt & 1) * 2];
                uint32_t bb1 = b[nt >> 1][(nt & 1) * 2 + 1];
                asm volatile(
                    "mma.sync.aligned.m16n8k16.row.col.f32.bf16.bf16.f32 "
                    "{%0,%1,%2,%3}, {%4,%5,%6,%7}, {%8,%9}, {%0,%1,%2,%3};"
                    : "+f"(acc[mt][nt][0]), "+f"(acc[mt][nt][1]),
                      "+f"(acc[mt][nt][2]), "+f"(acc[mt][nt][3])
                    : "r"(a[mt][0]), "r"(a[mt][1]), "r"(a[mt][2]), "r"(a[mt][3]),
                      "r"(bb0), "r"(bb1));
            }
    }
}

__device__ __forceinline__ void lse_exp_tile(
    int relvb, int span, const float* __restrict__ sbias,
    int nw, int t4, float acc[2][4][4], float sum0[2], float sum1[2])
{
#pragma unroll
    for (int nt = 0; nt < 4; nt++) {
        int i0 = relvb + nw * 32 + nt * 8 + t4 * 2;
        bool v0 = i0 < span, v1 = (i0 + 1) < span;
        float bb0 = v0 ? sbias[i0] : 0.f;
        float bb1 = v1 ? sbias[i0 + 1] : 0.f;
#pragma unroll
        for (int mt = 0; mt < 2; mt++) {
            if (v0) {
                sum0[mt] += __expf(acc[mt][nt][0] + bb0);
                sum1[mt] += __expf(acc[mt][nt][2] + bb0);
            }
            if (v1) {
                sum0[mt] += __expf(acc[mt][nt][1] + bb1);
                sum1[mt] += __expf(acc[mt][nt][3] + bb1);
            }
            acc[mt][nt][0] = acc[mt][nt][1] = acc[mt][nt][2] = acc[mt][nt][3] = 0.f;
        }
    }
}

// wait: epilogue col index uses nw*32? LBN=128 across 4 N-warps => 32 cols/warp. OK.

template <int NKK>
__device__ __forceinline__ void lse_run_bres(
    const __nv_bfloat16* __restrict__ A, const __nv_bfloat16* __restrict__ B,
    int V, int K, int mBase, int vb0, int nvb, int span,
    const float* __restrict__ sbias, uint32_t sbase, int tid,
    int lane, int mw, int nw, int t4,
    float acc[2][4][4], float sum0[2], float sum1[2])
{
    // stage 0: A rows (resident) + B tile 0; single-barrier 3-deep ring
#pragma unroll
    for (int i = 0; i < 2; i++) {
        int v = tid + i * 256;
        int row = v >> 3, cv = v & 7;
        if (cv * 8 < K)
            cpa16(sbase + (uint32_t)(row * LST + cv * 8) * 2u,
                  A + (size_t)(mBase + row) * K + cv * 8);
    }
    lse_prefetch_b(B, V, K, vb0, 0, sbase, tid);
    asm volatile("cp.async.commit_group;\n" ::);
#pragma unroll
    for (int s = 1; s < BSTG - 1; s++) {
        if (s < nvb)
            lse_prefetch_b(B, V, K, vb0 + s * LBN, s, sbase, tid);
        asm volatile("cp.async.commit_group;\n" ::);
    }
    for (int it = 0; it < nvb; it++) {
        asm volatile("cp.async.wait_group %0;\n" :: "n"(BSTG - 2));
        __syncthreads();
        int pf = it + BSTG - 1;
        if (pf < nvb)
            lse_prefetch_b(B, V, K, vb0 + pf * LBN, pf % BSTG, sbase, tid);
        asm volatile("cp.async.commit_group;\n" ::);

        uint32_t sBu = sbase + (uint32_t)(ASZ + (it % BSTG) * BSZ) * 2u;
        lse_mma_tile<NKK>(sbase, sBu, lane, mw, nw, acc);
        lse_exp_tile(it * LBN, span, sbias, nw, t4, acc, sum0, sum1);
    }
}

__global__ __launch_bounds__(256, 3) void k_lse(LseJobs jobs, float* __restrict__ partials) {
    extern __shared__ __align__(16) uint4 smem4[];
    __shared__ float s_red[LBM];
    __shared__ float s_bias_gen[256];

    const int cx = blockIdx.x;
    int ji = 3;
    if (cx < jobs.j[1].start) ji = 0;
    else if (cx < jobs.j[2].start) ji = 1;
    else if (cx < jobs.j[3].start) ji = 2;
    const LseJob jb = jobs.j[ji];
    const __nv_bfloat16* __restrict__ A = jb.A;
    const __nv_bfloat16* __restrict__ B = jb.B;
    const float* __restrict__ bias0 = jb.bias0;
    const float* __restrict__ bias1 = jb.bias1;
    const int V = jb.V, K = jb.K, bsplit = jb.bsplit;

    const int tid = threadIdx.x;
    const int lane = tid & 31, wid = tid >> 5;
    const int mw = wid >> 2, nw = wid & 3;    // 2(M) x 4(N)
    const int g = lane >> 2, t4 = lane & 3;
    const int mBase = blockIdx.y * LBM;
    const int vb0 = (cx - jb.start) * jb.vspan;
    const int span = min(jb.vspan, V - vb0);
    const int nvb = (span + LBN - 1) / LBN;
    const uint32_t sbase = (uint32_t)__cvta_generic_to_shared(smem4);

    if (tid < LBM) s_red[tid] = 0.f;

    float acc[2][4][4];
    float sum0[2] = {0.f, 0.f}, sum1[2] = {0.f, 0.f};
#pragma unroll
    for (int mt = 0; mt < 2; mt++)
#pragma unroll
        for (int nt = 0; nt < 4; nt++)
#pragma unroll
            for (int q = 0; q < 4; q++) acc[mt][nt][q] = 0.f;

    if (K <= 64) {
        float* sbias = reinterpret_cast<float*>(
            reinterpret_cast<char*>(smem4) + (ASZ + BSTG * BSZ) * 2);
        for (int i = tid; i < span; i += 256) {
            int c = vb0 + i;
            sbias[i] = (c < bsplit) ? bias0[c] : bias1[c - bsplit];
        }
        if (K == 16)
            lse_run_bres<1>(A, B, V, K, mBase, vb0, nvb, span, sbias, sbase, tid,
                            lane, mw, nw, t4, acc, sum0, sum1);
        else
            lse_run_bres<4>(A, B, V, K, mBase, vb0, nvb, span, sbias, sbase, tid,
                            lane, mw, nw, t4, acc, sum0, sum1);
    } else {
        for (int i = tid; i < span; i += 256) {
            int c = vb0 + i;
            s_bias_gen[i] = (c < bsplit) ? bias0[c] : bias1[c - bsplit];
        }
        const int nkb = K / LBK;
        const int NIT = nvb * nkb;
        // race-free 2-stage: pf(0), pf(1); loop { wait 1; sync; compute; sync; pf(it+2) }
        lse_prefetch(A, B, V, K, mBase, vb0, nkb, 0, 0, sbase, tid);
        asm volatile("cp.async.commit_group;\n" ::);
        if (1 < NIT)
            lse_prefetch(A, B, V, K, mBase, vb0, nkb, 1, 1, sbase, tid);
        asm volatile("cp.async.commit_group;\n" ::);

        for (int it = 0; it < NIT; it++) {
            asm volatile("cp.async.wait_group 1;\n" ::);
            __syncthreads();

            const int slot = it & 1;
            uint32_t sAu = sbase + (uint32_t)(slot * (ASZ + BSZ)) * 2u;
            lse_mma_tile<4>(sAu, sAu + (uint32_t)ASZ * 2u, lane, mw, nw, acc);

            int vbi = it / nkb;
            if (it - vbi * nkb == nkb - 1)
                lse_exp_tile(vbi * LBN, span, s_bias_gen, nw, t4, acc, sum0, sum1);

            __syncthreads();
            if (it + 2 < NIT)
                lse_prefetch(A, B, V, K, mBase, vb0, nkb, it + 2, slot, sbase, tid);
            asm volatile("cp.async.commit_group;\n" ::);
        }
    }

#pragma unroll
    for (int mt = 0; mt < 2; mt++) {
        float s0 = sum0[mt], s1 = sum1[mt];
        s0 += __shfl_xor_sync(0xffffffffu, s0, 1);
        s0 += __shfl_xor_sync(0xffffffffu, s0, 2);
        s1 += __shfl_xor_sync(0xffffffffu, s1, 1);
        s1 += __shfl_xor_sync(0xffffffffu, s1, 2);
        if (t4 == 0) {
            atomicAdd(&s_red[mw * 32 + mt * 16 + g], s0);
            atomicAdd(&s_red[mw * 32 + mt * 16 + g + 8], s1);
        }
    }
    __syncthreads();
    if (tid < LBM)
        partials[(size_t)(mBase + tid) * CH_STRIDE + cx] = s_red[tid];
}

// ---------------- finalize ----------------
__device__ __forceinline__ float blk_sum(float v, float* sbuf) {
#pragma unroll
    for (int o = 16; o; o >>= 1) v += __shfl_xor_sync(0xffffffffu, v, o);
    __syncthreads();
    if ((threadIdx.x & 31) == 0) sbuf[threadIdx.x >> 5] = v;
    __syncthreads();
    return sbuf[0] + sbuf[1] + sbuf[2] + sbuf[3];
}
__device__ __forceinline__ float blk_lse(const float* p, int n, float* sbuf) {
    float ls = 0.f;
    for (int i = threadIdx.x; i < n; i += 128) ls += p[i];
    float S = blk_sum(ls, sbuf);
    return logf(S);
}

__global__ __launch_bounds__(128) void k_final(
    const void* __restrict__ targetv,
    const float* __restrict__ projf,
    const float* __restrict__ W0, const float* __restrict__ b0,
    const float* __restrict__ cw, const float* __restrict__ cb,
    const float* __restrict__ W1, const float* __restrict__ b1,
    const float* __restrict__ W2, const float* __restrict__ b2,
    const float* __restrict__ W3, const float* __restrict__ b3,
    const float* __restrict__ partials,
    float* __restrict__ out)
{
    __shared__ float sred[4];
    const int r = blockIdx.x, tid = threadIdx.x;
    long long t;
    if (g_t64flag) t = ((const long long*)targetv)[r];
    else           t = (long long)((const int*)targetv)[r];
    t = t < 0 ? 0 : (t > 267734LL ? 267734LL : t);
    int c = (t < 19997) ? 0 : (t < 39997) ? 1 : (t < 199997) ? 2 : 3;

    const float* pr = projf + (size_t)r * 1024;
    const float* wr; float bv;
    if (c == 0) { wr = W0 + (size_t)t * 1024; bv = b0[t]; }
    else        { wr = cw + (size_t)(c - 1) * 1024; bv = cb[c - 1]; }
    float p = 0.f;
    for (int k = tid; k < 1024; k += 128) p += pr[k] * wr[k];
    float dot0 = blk_sum(p, sred) + bv;

    const float* ph = partials + (size_t)r * CH_STRIDE;
    float lse0 = blk_lse(ph + CH_OFF0, CH_N0, sred);
    float nll = lse0 - dot0;

    if (c > 0) {
        int Ki   = (c == 1) ? KD1 : (c == 2) ? KD2 : KD3;
        int poff = (c == 1) ? POFF1 : (c == 2) ? POFF2 : POFF3;
        const float* W  = (c == 1) ? W1 : (c == 2) ? W2 : W3;
        const float* bb = (c == 1) ? b1 : (c == 2) ? b2 : b3;
        long long l = (c == 1) ? 19997LL : (c == 2) ? 39997LL : 199997LL;
        long long rel = t - l;
        const float* pri = projf + poff + (size_t)r * Ki;
        const float* wri = W + (size_t)rel * Ki;
        float p2 = 0.f;
        for (int k = tid; k < Ki; k += 128) p2 += pri[k] * wri[k];
        float dotc = blk_sum(p2, sred) + bb[rel];
        int choff = (c == 1) ? CH_OFF1 : (c == 2) ? CH_OFF2 : CH_OFF3;
        int nch   = (c == 1) ? CH_N1 : (c == 2) ? CH_N2 : CH_N3;
        float lsec = blk_lse(ph + choff, nch, sred);
        nll += lsec - dotc;
    }
    if (tid == 0) out[r] = nll;
}

// ---------------- host ----------------
extern "C" void kernel_launch(void* const* d_in, const int* in_sizes, int n_in,
                              void* d_out, int out_size) {
    const float* hidden = (const float*)d_in[0];
    const void*  target = d_in[1];
    const float* W0 = (const float*)d_in[2];
    const float* b0 = (const float*)d_in[3];
    const float* p0 = (const float*)d_in[4];
    const float* W1 = (const float*)d_in[5];
    const float* b1 = (const float*)d_in[6];
    const float* p1 = (const float*)d_in[7];
    const float* W2 = (const float*)d_in[8];
    const float* b2 = (const float*)d_in[9];
    const float* p2 = (const float*)d_in[10];
    const float* W3 = (const float*)d_in[11];
    const float* b3 = (const float*)d_in[12];
    const float* p3 = (const float*)d_in[13];
    const float* cw = (const float*)d_in[14];
    const float* cb = (const float*)d_in[15];
    float* out = (float*)d_out;

    __nv_bfloat16 *Wbf, *hbf, *pTbf, *projbf;
    float* projf;
    float* parts;
    cudaGetSymbolAddress((void**)&Wbf, g_Wbf);
    cudaGetSymbolAddress((void**)&hbf, g_hbf);
    cudaGetSymbolAddress((void**)&pTbf, g_pTbf);
    cudaGetSymbolAddress((void**)&projf, g_projf);
    cudaGetSymbolAddress((void**)&projbf, g_projbf);
    cudaGetSymbolAddress((void**)&parts, g_partials);

    cudaFuncSetAttribute(k_lse, cudaFuncAttributeMaxDynamicSharedMemorySize, SMEM_DYN);

    // (1) merged prep
    {
        PrepArgs a;
        const float* srcs[6]  = {W0, cw, W1, W2, W3, hidden};
        __nv_bfloat16* dsts[6] = {Wbf + WOFF0, Wbf + WOFF0 + S0 * 1024,
                                  Wbf + WOFF1, Wbf + WOFF2, Wbf + WOFF3, hbf};
        long long cnts[6] = {(long long)S0 * 1024, 3 * 1024,
                             (long long)V1 * KD1, (long long)V2 * KD2,
                             (long long)V3 * KD3, (long long)NROWS * KD0};
        long long cum = 0;
        for (int i = 0; i < 6; i++) {
            a.cv.src[i] = srcs[i]; a.cv.dst[i] = dsts[i];
            a.cv.cum[i] = cum; cum += cnts[i] / 16;
        }
        a.cv.cum[6] = cum;
        a.total16 = cum;
        a.cvBlocks = (int)((cum + 255) / 256);
        a.tc.src[0] = p0; a.tc.dst[0] = pTbf + POFF0; a.tc.ncols[0] = 1024; a.tc.start[0] = 0;
        a.tc.src[1] = p1; a.tc.dst[1] = pTbf + POFF1; a.tc.ncols[1] = 256;  a.tc.start[1] = 32;
        a.tc.src[2] = p2; a.tc.dst[2] = pTbf + POFF2; a.tc.ncols[2] = 64;   a.tc.start[2] = 40;
        a.tc.src[3] = p3; a.tc.dst[3] = pTbf + POFF3; a.tc.ncols[3] = 16;   a.tc.start[3] = 42;
        int grid = a.cvBlocks + 43 * 32;
        k_prep<<<grid, 256>>>(a);
    }

    // (2) merged pipelined projections
    k_proj<<<dim3(22, 16), 256>>>(hbf, pTbf, projf, projbf);

    // (3) target dtype detection
    k_detect<<<1, 512>>>((const unsigned int*)target);

    // (4) merged fused logits + exp-sum  <-- launch #4: profiler lands here
    {
        LseJobs jobs;
        jobs.j[0] = { projbf + POFF0, Wbf + WOFF0, b0, cb, VHEAD, KD0, S0, CH_OFF0, 256 };
        jobs.j[1] = { projbf + POFF1, Wbf + WOFF1, b1, b1, V1, KD1, V1, CH_OFF1, 256 };
        jobs.j[2] = { projbf + POFF2, Wbf + WOFF2, b2, b2, V2, KD2, V2, CH_OFF2, 1024 };
        jobs.j[3] = { projbf + POFF3, Wbf + WOFF3, b3, b3, V3, KD3, V3, CH_OFF3, 1024 };
        k_lse<<<dim3(CH_STRIDE, 16), 256, SMEM_DYN>>>(jobs, parts);
    }

    // (5) finalize
    k_final<<<NROWS, 128>>>(target, projf, W0, b0, cw, cb, W1, b1, W2, b2, W3, b3,
                            parts, out);
}

// round 16
// speedup vs baseline: 1.0251x; 1.0251x over previous
#include <cuda_runtime.h>
#include <cuda_bf16.h>
#include <math.h>
#include <float.h>
#include <stdint.h>

// ---------------- problem constants ----------------
#define S0 19997
#define VHEAD 20000
#define V1 20000
#define V2 160000
#define V3 67738
#define KD0 1024
#define KD1 256
#define KD2 64
#define KD3 16
#define NROWS 1024

#define WOFF0 0
#define WOFF1 20480000
#define WOFF2 25600000
#define WOFF3 35840000
#define WTOT  36923808

#define POFF0 0
#define POFF1 1048576
#define POFF2 1310720
#define POFF3 1376256
#define PTOT  1392640

// partial exp-sum chunk layout: jobs 0,1 vspan=256; jobs 2,3 vspan=1024
#define CH_STRIDE 382
#define CH_OFF0 0
#define CH_N0   79
#define CH_OFF1 79
#define CH_N1   79
#define CH_OFF2 158
#define CH_N2   157
#define CH_OFF3 315
#define CH_N3   67

// ---------------- device scratch ----------------
__device__ __align__(16) __nv_bfloat16 g_Wbf[WTOT];
__device__ __align__(16) __nv_bfloat16 g_hbf[NROWS * KD0];
__device__ __align__(16) __nv_bfloat16 g_pTbf[PTOT];
__device__ __align__(16) float         g_projf[PTOT];
__device__ __align__(16) __nv_bfloat16 g_projbf[PTOT];
__device__ float         g_partials[NROWS * CH_STRIDE];
__device__ int           g_t64flag;

__device__ __forceinline__ void cpa16(uint32_t saddr, const void* g) {
    asm volatile("cp.async.cg.shared.global [%0], [%1], 16;\n" :: "r"(saddr), "l"(g));
}

// ---------------- target dtype detection ----------------
__global__ void k_detect(const unsigned int* __restrict__ t) {
    __shared__ int anynz;
    if (threadIdx.x == 0) anynz = 0;
    __syncthreads();
    if (t[2 * threadIdx.x + 1] != 0u) atomicOr(&anynz, 1);
    __syncthreads();
    if (threadIdx.x == 0) g_t64flag = anynz ? 0 : 1;
}

// ---------------- merged prep: wide convert (32 elems/thr) + transpose ----------
struct CvSegs {
    const float* src[6];
    __nv_bfloat16* dst[6];
    long long cum[7];     // cumulative counts in groups of 32 elements
};
struct TcJobs {
    const float* src[4];
    __nv_bfloat16* dst[4];
    int ncols[4];
    int start[4];
};
struct PrepArgs {
    CvSegs cv;
    TcJobs tc;
    long long total32;
    int cvBlocks;
};

__global__ __launch_bounds__(256) void k_prep(PrepArgs a) {
    if ((int)blockIdx.x < a.cvBlocks) {
        long long i = (long long)blockIdx.x * 256 + threadIdx.x;
        if (i >= a.total32) return;
        int j = 0;
#pragma unroll
        for (int k = 1; k < 6; k++)
            if (i >= a.cv.cum[k]) j = k;
        long long off = i - a.cv.cum[j];
        const float4* sp = reinterpret_cast<const float4*>(a.cv.src[j]) + off * 8;
        uint4* dp = reinterpret_cast<uint4*>(a.cv.dst[j]) + off * 4;
#pragma unroll
        for (int h = 0; h < 2; h++) {
            float4 v0 = sp[h * 4 + 0], v1 = sp[h * 4 + 1];
            float4 v2 = sp[h * 4 + 2], v3 = sp[h * 4 + 3];
            union { __nv_bfloat162 b[4]; uint4 u; } o0, o1;
            o0.b[0] = __floats2bfloat162_rn(v0.x, v0.y);
            o0.b[1] = __floats2bfloat162_rn(v0.z, v0.w);
            o0.b[2] = __floats2bfloat162_rn(v1.x, v1.y);
            o0.b[3] = __floats2bfloat162_rn(v1.z, v1.w);
            o1.b[0] = __floats2bfloat162_rn(v2.x, v2.y);
            o1.b[1] = __floats2bfloat162_rn(v2.z, v2.w);
            o1.b[2] = __floats2bfloat162_rn(v3.x, v3.y);
            o1.b[3] = __floats2bfloat162_rn(v3.z, v3.w);
            dp[h * 2 + 0] = o0.u;
            dp[h * 2 + 1] = o1.u;
        }
    } else {
        __shared__ float tile[32][33];
        int bx2 = blockIdx.x - a.cvBlocks;
        int xt = bx2 % 43;
        int byi = bx2 / 43;
        int ji = 3;
        if (xt < a.tc.start[1]) ji = 0;
        else if (xt < a.tc.start[2]) ji = 1;
        else if (xt < a.tc.start[3]) ji = 2;
        const float* src = a.tc.src[ji];
        __nv_bfloat16* dst = a.tc.dst[ji];
        const int ncols = a.tc.ncols[ji];
        int bx = (xt - a.tc.start[ji]) * 32;
        int by = byi * 32;
        int tx = threadIdx.x & 31, ty = threadIdx.x >> 5;
#pragma unroll
        for (int i = ty; i < 32; i += 8) {
            int k = by + i, j = bx + tx;
            if (j < ncols) tile[i][tx] = src[(size_t)k * ncols + j];
        }
        __syncthreads();
#pragma unroll
        for (int i = ty; i < 32; i += 8) {
            int j = bx + i, k = by + tx;
            if (j < ncols) dst[(size_t)j * 1024 + k] = __float2bfloat16(tile[tx][i]);
        }
    }
}

// ============================================================================
// Projection GEMM (mma.sync), 2-stage cp.async pipeline (race-free ordering).
// ============================================================================
#define GBM 64
#define GBN 64
#define GBK 64
#define SAST 80
#define PASZ (GBM * SAST)
#define PSTGB (2 * PASZ * 2)

__device__ __forceinline__ void proj_pf(
    const __nv_bfloat16* __restrict__ A, const __nv_bfloat16* __restrict__ B,
    int V, int K, int mBase, int vb, int kb, int slot, uint32_t sbase, int tid)
{
    uint32_t sA = sbase + (uint32_t)slot * PSTGB;
    uint32_t sB = sA + (uint32_t)PASZ * 2u;
#pragma unroll
    for (int i = 0; i < 2; i++) {
        int v = tid + i * 256;
        int row = v >> 3, cv = v & 7;
        int gk = kb + cv * 8;
        cpa16(sA + (uint32_t)(row * SAST + cv * 8) * 2u,
              A + (size_t)(mBase + row) * K + gk);
        int gr = vb + row;
        if (gr < V)
            cpa16(sB + (uint32_t)(row * SAST + cv * 8) * 2u,
                  B + (size_t)gr * K + gk);
    }
}

__device__ __forceinline__ void proj_tile(
    const __nv_bfloat16* __restrict__ A,
    const __nv_bfloat16* __restrict__ B,
    int V, int K, int mBase, int vb,
    float* __restrict__ Cf, __nv_bfloat16* __restrict__ Cbf,
    uint32_t sbase)
{
    const int tid = threadIdx.x;
    const int lane = tid & 31, wid = tid >> 5;
    const int mwarp = wid >> 1, nwarp = wid & 1;

    float acc[4][4];
#pragma unroll
    for (int a = 0; a < 4; a++)
#pragma unroll
        for (int b = 0; b < 4; b++) acc[a][b] = 0.f;

    const int nk = K / GBK;
    proj_pf(A, B, V, K, mBase, vb, 0, 0, sbase, tid);
    asm volatile("cp.async.commit_group;\n" ::);
    if (1 < nk) proj_pf(A, B, V, K, mBase, vb, GBK, 1, sbase, tid);
    asm volatile("cp.async.commit_group;\n" ::);

    for (int ik = 0; ik < nk; ik++) {
        asm volatile("cp.async.wait_group 1;\n" ::);
        __syncthreads();

        uint32_t sAu = sbase + (uint32_t)(ik & 1) * PSTGB;
        uint32_t sBu = sAu + (uint32_t)PASZ * 2u;
#pragma unroll
        for (int kk = 0; kk < 4; kk++) {
            uint32_t a0, a1, a2, a3;
            {
                int ar = mwarp * 16 + (lane & 15);
                int ac = kk * 16 + (lane >> 4) * 8;
                uint32_t addr = sAu + (uint32_t)(ar * SAST + ac) * 2u;
                asm volatile("ldmatrix.sync.aligned.m8n8.x4.shared.b16 {%0,%1,%2,%3}, [%4];"
                             : "=r"(a0), "=r"(a1), "=r"(a2), "=r"(a3) : "r"(addr));
            }
#pragma unroll
            for (int nt = 0; nt < 4; nt++) {
                uint32_t b0r, b1r;
                int br = nwarp * 32 + nt * 8 + (lane & 7);
                int bc = kk * 16 + ((lane >> 3) & 1) * 8;
                uint32_t addr = sBu + (uint32_t)(br * SAST + bc) * 2u;
                asm volatile("ldmatrix.sync.aligned.m8n8.x2.shared.b16 {%0,%1}, [%2];"
                             : "=r"(b0r), "=r"(b1r) : "r"(addr));
                asm volatile(
                    "mma.sync.aligned.m16n8k16.row.col.f32.bf16.bf16.f32 "
                    "{%0,%1,%2,%3}, {%4,%5,%6,%7}, {%8,%9}, {%0,%1,%2,%3};"
                    : "+f"(acc[nt][0]), "+f"(acc[nt][1]), "+f"(acc[nt][2]), "+f"(acc[nt][3])
                    : "r"(a0), "r"(a1), "r"(a2), "r"(a3), "r"(b0r), "r"(b1r));
            }
        }
        __syncthreads();
        if (ik + 2 < nk)
            proj_pf(A, B, V, K, mBase, vb, (ik + 2) * GBK, ik & 1, sbase, tid);
        asm volatile("cp.async.commit_group;\n" ::);
    }

    const int g = lane >> 2, t4 = lane & 3;
    const int r0 = mBase + mwarp * 16 + g, r1 = r0 + 8;
#pragma unroll
    for (int nt = 0; nt < 4; nt++) {
        int n0 = vb + nwarp * 32 + nt * 8 + t4 * 2;
        if (n0 < V) {
            Cf[(size_t)r0 * V + n0]     = acc[nt][0];
            Cf[(size_t)r0 * V + n0 + 1] = acc[nt][1];
            Cf[(size_t)r1 * V + n0]     = acc[nt][2];
            Cf[(size_t)r1 * V + n0 + 1] = acc[nt][3];
            Cbf[(size_t)r0 * V + n0]     = __float2bfloat16(acc[nt][0]);
            Cbf[(size_t)r0 * V + n0 + 1] = __float2bfloat16(acc[nt][1]);
            Cbf[(size_t)r1 * V + n0]     = __float2bfloat16(acc[nt][2]);
            Cbf[(size_t)r1 * V + n0 + 1] = __float2bfloat16(acc[nt][3]);
        }
    }
}

__global__ __launch_bounds__(256) void k_proj(
    const __nv_bfloat16* __restrict__ A, const __nv_bfloat16* __restrict__ pT,
    float* __restrict__ projf, __nv_bfloat16* __restrict__ projbf)
{
    __shared__ __align__(16) __nv_bfloat16 smem[2 * 2 * PASZ];
    uint32_t sbase = (uint32_t)__cvta_generic_to_shared(smem);
    int x = blockIdx.x;
    int mBase = blockIdx.y * GBM;
    if (x < 16)
        proj_tile(A, pT + POFF0, 1024, 1024, mBase, x * GBN, projf + POFF0, projbf + POFF0, sbase);
    else if (x < 20)
        proj_tile(A, pT + POFF1, 256, 1024, mBase, (x - 16) * GBN, projf + POFF1, projbf + POFF1, sbase);
    else if (x == 20)
        proj_tile(A, pT + POFF2, 64, 1024, mBase, 0, projf + POFF2, projbf + POFF2, sbase);
    else
        proj_tile(A, pT + POFF3, 16, 1024, mBase, 0, projf + POFF3, projbf + POFF3, sbase);
}

// ============================================================================
// Merged fused logits + exp-sum GEMM. Tiles 64x128x64, warps 2(M) x 4(N),
// occ 3. Grid SWAPPED: x = m-block (16), y = chunk (382) so the 16 CTAs
// sharing a B tile run concurrently (L2 reuse). All div/mod on the hot path
// strength-reduced to carried counters.
// ============================================================================
#define LBM 64
#define LBN 128
#define LBK 64
#define LST 72
#define ASZ (LBM * LST)
#define BSZ (LBN * LST)
#define NSTG 2
#define BSTG 3
#define SMEM_DYN 68608

struct LseJob {
    const __nv_bfloat16* A;
    const __nv_bfloat16* B;
    const float* bias0;
    const float* bias1;
    int V, K, bsplit, start, vspan;
};
struct LseJobs { LseJob j[4]; };

// generic prefetch with explicit (vb, kb)
__device__ __forceinline__ void lse_prefetch(
    const __nv_bfloat16* __restrict__ A, const __nv_bfloat16* __restrict__ B,
    int V, int K, int mBase, int vb, int kb, int slot,
    uint32_t sbase, int tid)
{
    uint32_t sA = sbase + (uint32_t)(slot * (ASZ + BSZ)) * 2u;
    uint32_t sB = sA + (uint32_t)ASZ * 2u;
#pragma unroll
    for (int i = 0; i < 2; i++) {
        int v = tid + i * 256;
        int row = v >> 3, cv = v & 7;
        cpa16(sA + (uint32_t)(row * LST + cv * 8) * 2u,
              A + (size_t)(mBase + row) * K + kb + cv * 8);
    }
#pragma unroll
    for (int i = 0; i < 4; i++) {
        int v = tid + i * 256;
        int row = v >> 3, cv = v & 7;
        int gr = vb + row;
        if (gr < V)
            cpa16(sB + (uint32_t)(row * LST + cv * 8) * 2u,
                  B + (size_t)gr * K + kb + cv * 8);
    }
}

__device__ __forceinline__ void lse_prefetch_b(
    const __nv_bfloat16* __restrict__ B,
    int V, int K, int vb, int slot,
    uint32_t sbase, int tid)
{
    uint32_t sB = sbase + (uint32_t)(ASZ + slot * BSZ) * 2u;
#pragma unroll
    for (int i = 0; i < 4; i++) {
        int v = tid + i * 256;
        int row = v >> 3, cv = v & 7;
        int gr = vb + row;
        if (gr < V && cv * 8 < K)
            cpa16(sB + (uint32_t)(row * LST + cv * 8) * 2u,
                  B + (size_t)gr * K + cv * 8);
    }
}

template <int NKK>
__device__ __forceinline__ void lse_mma_tile(
    uint32_t sAu, uint32_t sBu, int lane, int mw, int nw, float acc[2][4][4])
{
#pragma unroll
    for (int kk = 0; kk < NKK; kk++) {
        uint32_t a[2][4];
#pragma unroll
        for (int mt = 0; mt < 2; mt++) {
            int ar = mw * 32 + mt * 16 + (lane & 15);
            int ac = kk * 16 + (lane >> 4) * 8;
            uint32_t addr = sAu + (uint32_t)(ar * LST + ac) * 2u;
            asm volatile("ldmatrix.sync.aligned.m8n8.x4.shared.b16 {%0,%1,%2,%3}, [%4];"
                         : "=r"(a[mt][0]), "=r"(a[mt][1]), "=r"(a[mt][2]), "=r"(a[mt][3])
                         : "r"(addr));
        }
        uint32_t b[2][4];
#pragma unroll
        for (int np = 0; np < 2; np++) {
            int q = lane >> 3;
            int br = nw * 32 + np * 16 + (q >> 1) * 8 + (lane & 7);
            int bc = kk * 16 + (q & 1) * 8;
            uint32_t addr = sBu + (uint32_t)(br * LST + bc) * 2u;
            asm volatile("ldmatrix.sync.aligned.m8n8.x4.shared.b16 {%0,%1,%2,%3}, [%4];"
                         : "=r"(b[np][0]), "=r"(b[np][1]), "=r"(b[np][2]), "=r"(b[np][3])
                         : "r"(addr));
        }
#pragma unroll
        for (int mt = 0; mt < 2; mt++)
#pragma unroll
            for (int nt = 0; nt < 4; nt++) {
                uint32_t bb0 = b[nt >> 1][(nt & 1) * 2];
                uint32_t bb1 = b[nt >> 1][(nt & 1) * 2 + 1];
                asm volatile(
                    "mma.sync.aligned.m16n8k16.row.col.f32.bf16.bf16.f32 "
                    "{%0,%1,%2,%3}, {%4,%5,%6,%7}, {%8,%9}, {%0,%1,%2,%3};"
                    : "+f"(acc[mt][nt][0]), "+f"(acc[mt][nt][1]),
                      "+f"(acc[mt][nt][2]), "+f"(acc[mt][nt][3])
                    : "r"(a[mt][0]), "r"(a[mt][1]), "r"(a[mt][2]), "r"(a[mt][3]),
                      "r"(bb0), "r"(bb1));
            }
    }
}

__device__ __forceinline__ void lse_exp_tile(
    int relvb, int span, const float* __restrict__ sbias,
    int nw, int t4, float acc[2][4][4], float sum0[2], float sum1[2])
{
#pragma unroll
    for (int nt = 0; nt < 4; nt++) {
        int i0 = relvb + nw * 32 + nt * 8 + t4 * 2;
        bool v0 = i0 < span, v1 = (i0 + 1) < span;
        float bb0 = v0 ? sbias[i0] : 0.f;
        float bb1 = v1 ? sbias[i0 + 1] : 0.f;
#pragma unroll
        for (int mt = 0; mt < 2; mt++) {
            if (v0) {
                sum0[mt] += __expf(acc[mt][nt][0] + bb0);
                sum1[mt] += __expf(acc[mt][nt][2] + bb0);
            }
            if (v1) {
                sum0[mt] += __expf(acc[mt][nt][1] + bb1);
                sum1[mt] += __expf(acc[mt][nt][3] + bb1);
            }
            acc[mt][nt][0] = acc[mt][nt][1] = acc[mt][nt][2] = acc[mt][nt][3] = 0.f;
        }
    }
}

template <int NKK>
__device__ __forceinline__ void lse_run_bres(
    const __nv_bfloat16* __restrict__ A, const __nv_bfloat16* __restrict__ B,
    int V, int K, int mBase, int vb0, int nvb, int span,
    const float* __restrict__ sbias, uint32_t sbase, int tid,
    int lane, int mw, int nw, int t4,
    float acc[2][4][4], float sum0[2], float sum1[2])
{
#pragma unroll
    for (int i = 0; i < 2; i++) {
        int v = tid + i * 256;
        int row = v >> 3, cv = v & 7;
        if (cv * 8 < K)
            cpa16(sbase + (uint32_t)(row * LST + cv * 8) * 2u,
                  A + (size_t)(mBase + row) * K + cv * 8);
    }
    lse_prefetch_b(B, V, K, vb0, 0, sbase, tid);
    asm volatile("cp.async.commit_group;\n" ::);
#pragma unroll
    for (int s = 1; s < BSTG - 1; s++) {
        if (s < nvb)
            lse_prefetch_b(B, V, K, vb0 + s * LBN, s, sbase, tid);
        asm volatile("cp.async.commit_group;\n" ::);
    }
    // counters: slot = it % BSTG; pfslot = (it+2) % BSTG; relvb; pfvb
    int slot = 0, pfslot = (BSTG - 1) % BSTG;
    int relvb = 0;
    int pfvb = vb0 + (BSTG - 1) * LBN;
    for (int it = 0; it < nvb; it++) {
        asm volatile("cp.async.wait_group %0;\n" :: "n"(BSTG - 2));
        __syncthreads();
        if (it + BSTG - 1 < nvb)
            lse_prefetch_b(B, V, K, pfvb, pfslot, sbase, tid);
        asm volatile("cp.async.commit_group;\n" ::);

        uint32_t sBu = sbase + (uint32_t)(ASZ + slot * BSZ) * 2u;
        lse_mma_tile<NKK>(sbase, sBu, lane, mw, nw, acc);
        lse_exp_tile(relvb, span, sbias, nw, t4, acc, sum0, sum1);

        slot = (slot == BSTG - 1) ? 0 : slot + 1;
        pfslot = (pfslot == BSTG - 1) ? 0 : pfslot + 1;
        relvb += LBN;
        pfvb += LBN;
    }
}

__global__ __launch_bounds__(256, 3) void k_lse(LseJobs jobs, float* __restrict__ partials) {
    extern __shared__ __align__(16) uint4 smem4[];
    __shared__ float s_red[LBM];
    __shared__ float s_bias_gen[256];

    const int cx = blockIdx.y;         // chunk  (grid swapped for L2 reuse)
    const int mBase = blockIdx.x * LBM; // m-block
    int ji = 3;
    if (cx < jobs.j[1].start) ji = 0;
    else if (cx < jobs.j[2].start) ji = 1;
    else if (cx < jobs.j[3].start) ji = 2;
    const LseJob jb = jobs.j[ji];
    const __nv_bfloat16* __restrict__ A = jb.A;
    const __nv_bfloat16* __restrict__ B = jb.B;
    const float* __restrict__ bias0 = jb.bias0;
    const float* __restrict__ bias1 = jb.bias1;
    const int V = jb.V, K = jb.K, bsplit = jb.bsplit;

    const int tid = threadIdx.x;
    const int lane = tid & 31, wid = tid >> 5;
    const int mw = wid >> 2, nw = wid & 3;    // 2(M) x 4(N)
    const int g = lane >> 2, t4 = lane & 3;
    const int vb0 = (cx - jb.start) * jb.vspan;
    const int span = min(jb.vspan, V - vb0);
    const int nvb = (span + LBN - 1) / LBN;
    const uint32_t sbase = (uint32_t)__cvta_generic_to_shared(smem4);

    if (tid < LBM) s_red[tid] = 0.f;

    float acc[2][4][4];
    float sum0[2] = {0.f, 0.f}, sum1[2] = {0.f, 0.f};
#pragma unroll
    for (int mt = 0; mt < 2; mt++)
#pragma unroll
        for (int nt = 0; nt < 4; nt++)
#pragma unroll
            for (int q = 0; q < 4; q++) acc[mt][nt][q] = 0.f;

    if (K <= 64) {
        float* sbias = reinterpret_cast<float*>(
            reinterpret_cast<char*>(smem4) + (ASZ + BSTG * BSZ) * 2);
        for (int i = tid; i < span; i += 256) {
            int c = vb0 + i;
            sbias[i] = (c < bsplit) ? bias0[c] : bias1[c - bsplit];
        }
        if (K == 16)
            lse_run_bres<1>(A, B, V, K, mBase, vb0, nvb, span, sbias, sbase, tid,
                            lane, mw, nw, t4, acc, sum0, sum1);
        else
            lse_run_bres<4>(A, B, V, K, mBase, vb0, nvb, span, sbias, sbase, tid,
                            lane, mw, nw, t4, acc, sum0, sum1);
    } else {
        for (int i = tid; i < span; i += 256) {
            int c = vb0 + i;
            s_bias_gen[i] = (c < bsplit) ? bias0[c] : bias1[c - bsplit];
        }
        const int nkb = K / LBK;
        const int NIT = nvb * nkb;
        // prefetch it=0 and it=1 (explicit coords; nkb>=2 always here since K>=256)
        lse_prefetch(A, B, V, K, mBase, vb0, 0, 0, sbase, tid);
        asm volatile("cp.async.commit_group;\n" ::);
        if (1 < NIT)
            lse_prefetch(A, B, V, K, mBase, vb0, LBK, 1, sbase, tid);
        asm volatile("cp.async.commit_group;\n" ::);

        // carried counters: compute coords (ckbi, crelvb); prefetch coords for it+2
        int ckbi = 0, crelvb = 0;
        int pkbi = 2 % nkb;                  // one-time
        int pvb = vb0 + (2 / nkb) * LBN;     // one-time
        for (int it = 0; it < NIT; it++) {
            asm volatile("cp.async.wait_group 1;\n" ::);
            __syncthreads();

            const int slot = it & 1;
            uint32_t sAu = sbase + (uint32_t)(slot * (ASZ + BSZ)) * 2u;
            lse_mma_tile<4>(sAu, sAu + (uint32_t)ASZ * 2u, lane, mw, nw, acc);

            bool lastk = (ckbi == nkb - 1);
            if (lastk)
                lse_exp_tile(crelvb, span, s_bias_gen, nw, t4, acc, sum0, sum1);

            __syncthreads();
            if (it + 2 < NIT)
                lse_prefetch(A, B, V, K, mBase, pvb, pkbi * LBK, slot, sbase, tid);
            asm volatile("cp.async.commit_group;\n" ::);

            if (lastk) { ckbi = 0; crelvb += LBN; } else ckbi++;
            if (pkbi == nkb - 1) { pkbi = 0; pvb += LBN; } else pkbi++;
        }
    }

#pragma unroll
    for (int mt = 0; mt < 2; mt++) {
        float s0 = sum0[mt], s1 = sum1[mt];
        s0 += __shfl_xor_sync(0xffffffffu, s0, 1);
        s0 += __shfl_xor_sync(0xffffffffu, s0, 2);
        s1 += __shfl_xor_sync(0xffffffffu, s1, 1);
        s1 += __shfl_xor_sync(0xffffffffu, s1, 2);
        if (t4 == 0) {
            atomicAdd(&s_red[mw * 32 + mt * 16 + g], s0);
            atomicAdd(&s_red[mw * 32 + mt * 16 + g + 8], s1);
        }
    }
    __syncthreads();
    if (tid < LBM)
        partials[(size_t)(mBase + tid) * CH_STRIDE + cx] = s_red[tid];
}

// ---------------- finalize ----------------
__device__ __forceinline__ float blk_sum(float v, float* sbuf) {
#pragma unroll
    for (int o = 16; o; o >>= 1) v += __shfl_xor_sync(0xffffffffu, v, o);
    __syncthreads();
    if ((threadIdx.x & 31) == 0) sbuf[threadIdx.x >> 5] = v;
    __syncthreads();
    return sbuf[0] + sbuf[1] + sbuf[2] + sbuf[3];
}
__device__ __forceinline__ float blk_lse(const float* p, int n, float* sbuf) {
    float ls = 0.f;
    for (int i = threadIdx.x; i < n; i += 128) ls += p[i];
    float S = blk_sum(ls, sbuf);
    return logf(S);
}

__global__ __launch_bounds__(128) void k_final(
    const void* __restrict__ targetv,
    const float* __restrict__ projf,
    const float* __restrict__ W0, const float* __restrict__ b0,
    const float* __restrict__ cw, const float* __restrict__ cb,
    const float* __restrict__ W1, const float* __restrict__ b1,
    const float* __restrict__ W2, const float* __restrict__ b2,
    const float* __restrict__ W3, const float* __restrict__ b3,
    const float* __restrict__ partials,
    float* __restrict__ out)
{
    __shared__ float sred[4];
    const int r = blockIdx.x, tid = threadIdx.x;
    long long t;
    if (g_t64flag) t = ((const long long*)targetv)[r];
    else           t = (long long)((const int*)targetv)[r];
    t = t < 0 ? 0 : (t > 267734LL ? 267734LL : t);
    int c = (t < 19997) ? 0 : (t < 39997) ? 1 : (t < 199997) ? 2 : 3;

    const float* pr = projf + (size_t)r * 1024;
    const float* wr; float bv;
    if (c == 0) { wr = W0 + (size_t)t * 1024; bv = b0[t]; }
    else        { wr = cw + (size_t)(c - 1) * 1024; bv = cb[c - 1]; }
    float p = 0.f;
    for (int k = tid; k < 1024; k += 128) p += pr[k] * wr[k];
    float dot0 = blk_sum(p, sred) + bv;

    const float* ph = partials + (size_t)r * CH_STRIDE;
    float lse0 = blk_lse(ph + CH_OFF0, CH_N0, sred);
    float nll = lse0 - dot0;

    if (c > 0) {
        int Ki   = (c == 1) ? KD1 : (c == 2) ? KD2 : KD3;
        int poff = (c == 1) ? POFF1 : (c == 2) ? POFF2 : POFF3;
        const float* W  = (c == 1) ? W1 : (c == 2) ? W2 : W3;
        const float* bb = (c == 1) ? b1 : (c == 2) ? b2 : b3;
        long long l = (c == 1) ? 19997LL : (c == 2) ? 39997LL : 199997LL;
        long long rel = t - l;
        const float* pri = projf + poff + (size_t)r * Ki;
        const float* wri = W + (size_t)rel * Ki;
        float p2 = 0.f;
        for (int k = tid; k < Ki; k += 128) p2 += pri[k] * wri[k];
        float dotc = blk_sum(p2, sred) + bb[rel];
        int choff = (c == 1) ? CH_OFF1 : (c == 2) ? CH_OFF2 : CH_OFF3;
        int nch   = (c == 1) ? CH_N1 : (c == 2) ? CH_N2 : CH_N3;
        float lsec = blk_lse(ph + choff, nch, sred);
        nll += lsec - dotc;
    }
    if (tid == 0) out[r] = nll;
}

// ---------------- host ----------------
extern "C" void kernel_launch(void* const* d_in, const int* in_sizes, int n_in,
                              void* d_out, int out_size) {
    const float* hidden = (const float*)d_in[0];
    const void*  target = d_in[1];
    const float* W0 = (const float*)d_in[2];
    const float* b0 = (const float*)d_in[3];
    const float* p0 = (const float*)d_in[4];
    const float* W1 = (const float*)d_in[5];
    const float* b1 = (const float*)d_in[6];
    const float* p1 = (const float*)d_in[7];
    const float* W2 = (const float*)d_in[8];
    const float* b2 = (const float*)d_in[9];
    const float* p2 = (const float*)d_in[10];
    const float* W3 = (const float*)d_in[11];
    const float* b3 = (const float*)d_in[12];
    const float* p3 = (const float*)d_in[13];
    const float* cw = (const float*)d_in[14];
    const float* cb = (const float*)d_in[15];
    float* out = (float*)d_out;

    __nv_bfloat16 *Wbf, *hbf, *pTbf, *projbf;
    float* projf;
    float* parts;
    cudaGetSymbolAddress((void**)&Wbf, g_Wbf);
    cudaGetSymbolAddress((void**)&hbf, g_hbf);
    cudaGetSymbolAddress((void**)&pTbf, g_pTbf);
    cudaGetSymbolAddress((void**)&projf, g_projf);
    cudaGetSymbolAddress((void**)&projbf, g_projbf);
    cudaGetSymbolAddress((void**)&parts, g_partials);

    cudaFuncSetAttribute(k_lse, cudaFuncAttributeMaxDynamicSharedMemorySize, SMEM_DYN);

    // (1) merged prep (32 elems/thread convert)
    {
        PrepArgs a;
        const float* srcs[6]  = {W0, cw, W1, W2, W3, hidden};
        __nv_bfloat16* dsts[6] = {Wbf + WOFF0, Wbf + WOFF0 + S0 * 1024,
                                  Wbf + WOFF1, Wbf + WOFF2, Wbf + WOFF3, hbf};
        long long cnts[6] = {(long long)S0 * 1024, 3 * 1024,
                             (long long)V1 * KD1, (long long)V2 * KD2,
                             (long long)V3 * KD3, (long long)NROWS * KD0};
        long long cum = 0;
        for (int i = 0; i < 6; i++) {
            a.cv.src[i] = srcs[i]; a.cv.dst[i] = dsts[i];
            a.cv.cum[i] = cum; cum += cnts[i] / 32;
        }
        a.cv.cum[6] = cum;
        a.total32 = cum;
        a.cvBlocks = (int)((cum + 255) / 256);
        a.tc.src[0] = p0; a.tc.dst[0] = pTbf + POFF0; a.tc.ncols[0] = 1024; a.tc.start[0] = 0;
        a.tc.src[1] = p1; a.tc.dst[1] = pTbf + POFF1; a.tc.ncols[1] = 256;  a.tc.start[1] = 32;
        a.tc.src[2] = p2; a.tc.dst[2] = pTbf + POFF2; a.tc.ncols[2] = 64;   a.tc.start[2] = 40;
        a.tc.src[3] = p3; a.tc.dst[3] = pTbf + POFF3; a.tc.ncols[3] = 16;   a.tc.start[3] = 42;
        int grid = a.cvBlocks + 43 * 32;
        k_prep<<<grid, 256>>>(a);
    }

    // (2) merged pipelined projections
    k_proj<<<dim3(22, 16), 256>>>(hbf, pTbf, projf, projbf);

    // (3) target dtype detection
    k_detect<<<1, 512>>>((const unsigned int*)target);

    // (4) merged fused logits + exp-sum  <-- launch #4: profiler lands here
    {
        LseJobs jobs;
        jobs.j[0] = { projbf + POFF0, Wbf + WOFF0, b0, cb, VHEAD, KD0, S0, CH_OFF0, 256 };
        jobs.j[1] = { projbf + POFF1, Wbf + WOFF1, b1, b1, V1, KD1, V1, CH_OFF1, 256 };
        jobs.j[2] = { projbf + POFF2, Wbf + WOFF2, b2, b2, V2, KD2, V2, CH_OFF2, 1024 };
        jobs.j[3] = { projbf + POFF3, Wbf + WOFF3, b3, b3, V3, KD3, V3, CH_OFF3, 1024 };
        k_lse<<<dim3(16, CH_STRIDE), 256, SMEM_DYN>>>(jobs, parts);
    }

    // (5) finalize
    k_final<<<NROWS, 128>>>(target, projf, W0, b0, cw, cb, W1, b1, W2, b2, W3, b3,
                            parts, out);
}